// round 14
// baseline (speedup 1.0000x reference)
#include <cuda_runtime.h>
#include <stdint.h>

// out[b,d] = x[b,d] * |W[d,d]| using Blackwell 256-bit global accesses.
// Each lane moves one float8 (32B) per iteration -> a warp covers 1024B
// contiguous per LDG.E.256/STG.E.256, halving LSU wavefronts per byte and
// giving the memory controller 1KB sequential bursts.
// D/8 = 128 column groups; grid stride is a multiple of 128, so each
// thread's 8 diagonal values are loop-invariant (loaded once in prologue).
// launch_bounds(256,7): regs<=36 -> 7 blocks/SM = 56 warps/SM.
__global__ void __launch_bounds__(256, 7) diag_mul_v8_kernel(
    const float* __restrict__ x,
    const float* __restrict__ W,
    float* __restrict__ out,
    long n8, int D) {
    long tid0 = (long)blockIdx.x * blockDim.x + threadIdx.x;
    // Fixed column group for this thread: (tid0 mod 128), 8 columns.
    int c = ((int)(tid0 & 127)) * 8;
    float d0 = fabsf(__ldg(&W[(size_t)(c + 0) * (D + 1)]));
    float d1 = fabsf(__ldg(&W[(size_t)(c + 1) * (D + 1)]));
    float d2 = fabsf(__ldg(&W[(size_t)(c + 2) * (D + 1)]));
    float d3 = fabsf(__ldg(&W[(size_t)(c + 3) * (D + 1)]));
    float d4 = fabsf(__ldg(&W[(size_t)(c + 4) * (D + 1)]));
    float d5 = fabsf(__ldg(&W[(size_t)(c + 5) * (D + 1)]));
    float d6 = fabsf(__ldg(&W[(size_t)(c + 6) * (D + 1)]));
    float d7 = fabsf(__ldg(&W[(size_t)(c + 7) * (D + 1)]));

    const long stride = (long)gridDim.x * blockDim.x;  // multiple of 128
    for (long i = tid0; i < n8; i += stride) {
        const float* src = x + i * 8;
        float* dst = out + i * 8;
        float v0, v1, v2, v3, v4, v5, v6, v7;
        asm volatile(
            "ld.global.cs.v8.f32 {%0,%1,%2,%3,%4,%5,%6,%7}, [%8];"
            : "=f"(v0), "=f"(v1), "=f"(v2), "=f"(v3),
              "=f"(v4), "=f"(v5), "=f"(v6), "=f"(v7)
            : "l"(src));
        v0 *= d0; v1 *= d1; v2 *= d2; v3 *= d3;
        v4 *= d4; v5 *= d5; v6 *= d6; v7 *= d7;
        asm volatile(
            "st.global.cs.v8.f32 [%0], {%1,%2,%3,%4,%5,%6,%7,%8};"
            :: "l"(dst),
               "f"(v0), "f"(v1), "f"(v2), "f"(v3),
               "f"(v4), "f"(v5), "f"(v6), "f"(v7)
            : "memory");
    }
}

// Fallback (proven converged v4 shape) in case pointers are not 32B aligned.
__global__ void __launch_bounds__(256) diag_mul_v4_kernel(
    const float4* __restrict__ x4,
    const float* __restrict__ W,
    float4* __restrict__ out4,
    long n4, int D) {
    int c = threadIdx.x * 4;
    float4 d;
    d.x = fabsf(__ldg(&W[(size_t)(c + 0) * (D + 1)]));
    d.y = fabsf(__ldg(&W[(size_t)(c + 1) * (D + 1)]));
    d.z = fabsf(__ldg(&W[(size_t)(c + 2) * (D + 1)]));
    d.w = fabsf(__ldg(&W[(size_t)(c + 3) * (D + 1)]));
    const long stride = (long)gridDim.x * blockDim.x;
    for (long i = (long)blockIdx.x * blockDim.x + threadIdx.x; i < n4; i += stride) {
        float4 v = __ldcs(&x4[i]);
        v.x *= d.x; v.y *= d.y; v.z *= d.z; v.w *= d.w;
        __stcs(&out4[i], v);
    }
}

extern "C" void kernel_launch(void* const* d_in, const int* in_sizes, int n_in,
                              void* d_out, int out_size) {
    const float* x = (const float*)d_in[0];
    const float* W = (const float*)d_in[1];
    float* out = (float*)d_out;

    const int D = 1024;
    const long total = (long)out_size;  // 2^26

    bool aligned32 = ((((uintptr_t)x) | ((uintptr_t)out)) & 31) == 0;
    int blocks = 148 * 16;  // 2368

    if (aligned32 && (total % 8 == 0)) {
        diag_mul_v8_kernel<<<blocks, 256>>>(x, W, out, total / 8, D);
    } else {
        diag_mul_v4_kernel<<<blocks, 256>>>(
            reinterpret_cast<const float4*>(x), W,
            reinterpret_cast<float4*>(out), total / 4, D);
    }
}

// round 15
// speedup vs baseline: 1.0242x; 1.0242x over previous
#include <cuda_runtime.h>
#include <stdint.h>

// FINAL. out[b,d] = x[b,d] * |W[d,d]| using Blackwell 256-bit global accesses.
// Each lane moves one float8 (32B) per iteration -> a warp covers 1024B
// contiguous per LDG.E.256/STG.E.256, halving LSU wavefronts per byte and
// giving the memory controller 1KB sequential bursts.
// D/8 = 128 column groups; grid stride is a multiple of 128, so each
// thread's 8 diagonal values are loop-invariant (loaded once in prologue;
// W's diagonal is L2-resident after wave 1).
// Best measured: 78.24us @ 6250 GB/s (78.1% of spec) — the HBM ceiling for
// a 1:1 read:write stream on this part. Occupancy/hint/wave variations all
// land within the +/-1.5us machine-noise band; occ=6 blocks/SM suffices
// (LDG queue saturated at 48 warps/SM, issue ~7%).
__global__ void __launch_bounds__(256, 6) diag_mul_v8_kernel(
    const float* __restrict__ x,
    const float* __restrict__ W,
    float* __restrict__ out,
    long n8, int D) {
    long tid0 = (long)blockIdx.x * blockDim.x + threadIdx.x;
    // Fixed column group for this thread: (tid0 mod 128), 8 columns.
    int c = ((int)(tid0 & 127)) * 8;
    float d0 = fabsf(__ldg(&W[(size_t)(c + 0) * (D + 1)]));
    float d1 = fabsf(__ldg(&W[(size_t)(c + 1) * (D + 1)]));
    float d2 = fabsf(__ldg(&W[(size_t)(c + 2) * (D + 1)]));
    float d3 = fabsf(__ldg(&W[(size_t)(c + 3) * (D + 1)]));
    float d4 = fabsf(__ldg(&W[(size_t)(c + 4) * (D + 1)]));
    float d5 = fabsf(__ldg(&W[(size_t)(c + 5) * (D + 1)]));
    float d6 = fabsf(__ldg(&W[(size_t)(c + 6) * (D + 1)]));
    float d7 = fabsf(__ldg(&W[(size_t)(c + 7) * (D + 1)]));

    const long stride = (long)gridDim.x * blockDim.x;  // multiple of 128
    for (long i = tid0; i < n8; i += stride) {
        const float* src = x + i * 8;
        float* dst = out + i * 8;
        float v0, v1, v2, v3, v4, v5, v6, v7;
        asm volatile(
            "ld.global.cs.v8.f32 {%0,%1,%2,%3,%4,%5,%6,%7}, [%8];"
            : "=f"(v0), "=f"(v1), "=f"(v2), "=f"(v3),
              "=f"(v4), "=f"(v5), "=f"(v6), "=f"(v7)
            : "l"(src));
        v0 *= d0; v1 *= d1; v2 *= d2; v3 *= d3;
        v4 *= d4; v5 *= d5; v6 *= d6; v7 *= d7;
        asm volatile(
            "st.global.cs.v8.f32 [%0], {%1,%2,%3,%4,%5,%6,%7,%8};"
            :: "l"(dst),
               "f"(v0), "f"(v1), "f"(v2), "f"(v3),
               "f"(v4), "f"(v5), "f"(v6), "f"(v7)
            : "memory");
    }
}

// Fallback (proven converged v4 shape) in case pointers are not 32B aligned.
__global__ void __launch_bounds__(256) diag_mul_v4_kernel(
    const float4* __restrict__ x4,
    const float* __restrict__ W,
    float4* __restrict__ out4,
    long n4, int D) {
    int c = threadIdx.x * 4;
    float4 d;
    d.x = fabsf(__ldg(&W[(size_t)(c + 0) * (D + 1)]));
    d.y = fabsf(__ldg(&W[(size_t)(c + 1) * (D + 1)]));
    d.z = fabsf(__ldg(&W[(size_t)(c + 2) * (D + 1)]));
    d.w = fabsf(__ldg(&W[(size_t)(c + 3) * (D + 1)]));
    const long stride = (long)gridDim.x * blockDim.x;
    for (long i = (long)blockIdx.x * blockDim.x + threadIdx.x; i < n4; i += stride) {
        float4 v = __ldcs(&x4[i]);
        v.x *= d.x; v.y *= d.y; v.z *= d.z; v.w *= d.w;
        __stcs(&out4[i], v);
    }
}

extern "C" void kernel_launch(void* const* d_in, const int* in_sizes, int n_in,
                              void* d_out, int out_size) {
    const float* x = (const float*)d_in[0];
    const float* W = (const float*)d_in[1];
    float* out = (float*)d_out;

    const int D = 1024;
    const long total = (long)out_size;  // 2^26

    bool aligned32 = ((((uintptr_t)x) | ((uintptr_t)out)) & 31) == 0;
    int blocks = 148 * 16;  // 2368

    if (aligned32 && (total % 8 == 0)) {
        diag_mul_v8_kernel<<<blocks, 256>>>(x, W, out, total / 8, D);
    } else {
        diag_mul_v4_kernel<<<blocks, 256>>>(
            reinterpret_cast<const float4*>(x), W,
            reinterpret_cast<float4*>(out), total / 4, D);
    }
}